// round 1
// baseline (speedup 1.0000x reference)
#include <cuda_runtime.h>
#include <mma.h>

using namespace nvcuda;

#define SEQ 4096
#define EMB 1024
#define NH  16
#define HD  64

// Scratch (allowed: __device__ globals, no runtime allocation)
__device__ float g_Q[NH * SEQ * HD];   // [h][s][d], pre-scaled by 1/sqrt(64)
__device__ float g_K[NH * SEQ * HD];   // [h][s][d]
__device__ float g_V[NH * SEQ * HD];   // [h][s][d]
__device__ float g_O[SEQ * EMB];       // [s][e] attention output before Wo

// ---------------------------------------------------------------------------
// TF32 wmma GEMM:  C = (A[4096x1024] @ W[1024x1024] + bias) * scale
// head_split=1 -> write [h][s][d] layout; else flat [s][n]
// Block tile 128x64, K-tile 16, 256 threads = 8 warps (4 row x 2 col of 32x32)
// ---------------------------------------------------------------------------
__global__ __launch_bounds__(256) void proj_gemm(
    const float* __restrict__ A, const float* __restrict__ W,
    const float* __restrict__ bias, float* __restrict__ C,
    float scale, int head_split)
{
    const int BM = 128, BN = 64, BK = 16;
    __shared__ float As[BM * BK];
    __shared__ float Bs[BK * BN];
    __shared__ float Cs[BM * BN];

    const int m0 = blockIdx.y * BM;
    const int n0 = blockIdx.x * BN;
    const int tid = threadIdx.x;
    const int wid = tid >> 5;
    const int wr = wid & 3;   // warp row 0..3 (16*2 rows each)
    const int wc = wid >> 2;  // warp col 0..1 (32 cols each)

    wmma::fragment<wmma::accumulator, 16, 16, 8, float> acc[2][2];
#pragma unroll
    for (int i = 0; i < 2; i++)
#pragma unroll
        for (int j = 0; j < 2; j++) wmma::fill_fragment(acc[i][j], 0.0f);

    for (int k0 = 0; k0 < EMB; k0 += BK) {
        // A tile: 128x16 floats = 512 float4
#pragma unroll
        for (int i = tid; i < 512; i += 256) {
            int r = i >> 2, c = (i & 3) << 2;
            *(float4*)&As[r * BK + c] =
                *(const float4*)&A[(m0 + r) * EMB + k0 + c];
        }
        // B tile: 16x64 floats = 256 float4
        {
            int r = tid >> 4, c = (tid & 15) << 2;
            *(float4*)&Bs[r * BN + c] =
                *(const float4*)&W[(k0 + r) * EMB + n0 + c];
        }
        __syncthreads();

#pragma unroll
        for (int ks = 0; ks < 2; ks++) {
            wmma::fragment<wmma::matrix_a, 16, 16, 8, wmma::precision::tf32,
                           wmma::row_major> af[2];
            wmma::fragment<wmma::matrix_b, 16, 16, 8, wmma::precision::tf32,
                           wmma::row_major> bf[2];
#pragma unroll
            for (int i = 0; i < 2; i++) {
                wmma::load_matrix_sync(af[i], &As[(wr * 32 + i * 16) * BK + ks * 8], BK);
                for (int t = 0; t < af[i].num_elements; t++)
                    af[i].x[t] = wmma::__float_to_tf32(af[i].x[t]);
            }
#pragma unroll
            for (int j = 0; j < 2; j++) {
                wmma::load_matrix_sync(bf[j], &Bs[(ks * 8) * BN + wc * 32 + j * 16], BN);
                for (int t = 0; t < bf[j].num_elements; t++)
                    bf[j].x[t] = wmma::__float_to_tf32(bf[j].x[t]);
            }
#pragma unroll
            for (int i = 0; i < 2; i++)
#pragma unroll
                for (int j = 0; j < 2; j++)
                    wmma::mma_sync(acc[i][j], af[i], bf[j], acc[i][j]);
        }
        __syncthreads();
    }

    // stage accumulators
#pragma unroll
    for (int i = 0; i < 2; i++)
#pragma unroll
        for (int j = 0; j < 2; j++)
            wmma::store_matrix_sync(&Cs[(wr * 32 + i * 16) * BN + wc * 32 + j * 16],
                                    acc[i][j], BN, wmma::mem_row_major);
    __syncthreads();

    // epilogue: bias + scale + layout
    for (int i = tid; i < (BM * BN) / 4; i += 256) {
        int r = i >> 4, c = (i & 15) << 2;
        float4 v = *(float4*)&Cs[r * BN + c];
        int n = n0 + c;
        int s = m0 + r;
        v.x = (v.x + bias[n + 0]) * scale;
        v.y = (v.y + bias[n + 1]) * scale;
        v.z = (v.z + bias[n + 2]) * scale;
        v.w = (v.w + bias[n + 3]) * scale;
        if (head_split) {
            int h = n >> 6, d = n & 63;
            *(float4*)&C[(h * SEQ + s) * HD + d] = v;
        } else {
            *(float4*)&C[s * EMB + n] = v;
        }
    }
}

// ---------------------------------------------------------------------------
// Flash attention, one CTA per (64-row q tile, head). TF32 wmma for both
// QK^T and PV; fp32 online softmax. 256 threads = 8 warps (4x2 of 16x32).
// Dynamic SMEM: Qs,Ks,Vs,Ss,Os (64x64 f32 each) + m,l rows = 82432 B.
// ---------------------------------------------------------------------------
__global__ __launch_bounds__(256) void flash_attn()
{
    extern __shared__ float sm[];
    float* Qs = sm;                 // 4096
    float* Ks = sm + 4096;          // 4096
    float* Vs = sm + 8192;          // 4096
    float* Ss = sm + 12288;         // 4096  (scores -> probs)
    float* Os = sm + 16384;         // 4096  (output accumulator)
    float* mrow = sm + 20480;       // 64
    float* lrow = mrow + 64;        // 64

    const int h = blockIdx.y;
    const int q0 = blockIdx.x * 64;
    const int tid = threadIdx.x;
    const int wid = tid >> 5;
    const int wr = wid & 3;   // 0..3 (16 rows each)
    const int wc = wid >> 2;  // 0..1 (32 cols each)

    const float* Qg = g_Q + (h * SEQ + q0) * HD;
    for (int i = tid; i < 1024; i += 256) {
        int r = i >> 4, c = (i & 15) << 2;
        *(float4*)&Qs[r * 64 + c] = *(const float4*)&Qg[r * HD + c];
        *(float4*)&Os[r * 64 + c] = make_float4(0.f, 0.f, 0.f, 0.f);
    }
    if (tid < 64) { mrow[tid] = -1e30f; lrow[tid] = 0.0f; }
    __syncthreads();

    const int row = tid >> 2;   // 0..63  (4 threads per row)
    const int sub = tid & 3;

    for (int t = 0; t < SEQ / 64; t++) {
        const float* Kg = g_K + (h * SEQ + t * 64) * HD;
        const float* Vg = g_V + (h * SEQ + t * 64) * HD;
        for (int i = tid; i < 1024; i += 256) {
            int r = i >> 4, c = (i & 15) << 2;
            *(float4*)&Ks[r * 64 + c] = *(const float4*)&Kg[r * HD + c];
            *(float4*)&Vs[r * 64 + c] = *(const float4*)&Vg[r * HD + c];
        }
        __syncthreads();

        // ---- S = Qs @ Ks^T  (Ks rows are keys, so matrix_b is col_major) ----
        {
            wmma::fragment<wmma::accumulator, 16, 16, 8, float> sacc[2];
            wmma::fill_fragment(sacc[0], 0.f);
            wmma::fill_fragment(sacc[1], 0.f);
#pragma unroll
            for (int kk = 0; kk < 8; kk++) {
                wmma::fragment<wmma::matrix_a, 16, 16, 8, wmma::precision::tf32,
                               wmma::row_major> af;
                wmma::load_matrix_sync(af, &Qs[(wr * 16) * 64 + kk * 8], 64);
                for (int e = 0; e < af.num_elements; e++)
                    af.x[e] = wmma::__float_to_tf32(af.x[e]);
#pragma unroll
                for (int j = 0; j < 2; j++) {
                    wmma::fragment<wmma::matrix_b, 16, 16, 8, wmma::precision::tf32,
                                   wmma::col_major> bf;
                    wmma::load_matrix_sync(bf, &Ks[(wc * 32 + j * 16) * 64 + kk * 8], 64);
                    for (int e = 0; e < bf.num_elements; e++)
                        bf.x[e] = wmma::__float_to_tf32(bf.x[e]);
                    wmma::mma_sync(sacc[j], af, bf, sacc[j]);
                }
            }
            wmma::store_matrix_sync(&Ss[(wr * 16) * 64 + wc * 32], sacc[0], 64,
                                    wmma::mem_row_major);
            wmma::store_matrix_sync(&Ss[(wr * 16) * 64 + wc * 32 + 16], sacc[1], 64,
                                    wmma::mem_row_major);
        }
        __syncthreads();

        // ---- online softmax (4 threads per row, quads are lane-contiguous) ----
        {
            const int cb = sub * 16;
            float tmax = -1e30f;
#pragma unroll
            for (int c = 0; c < 16; c++) tmax = fmaxf(tmax, Ss[row * 64 + cb + c]);
            tmax = fmaxf(tmax, __shfl_xor_sync(0xffffffffu, tmax, 1));
            tmax = fmaxf(tmax, __shfl_xor_sync(0xffffffffu, tmax, 2));
            float mold = mrow[row];
            float mnew = fmaxf(mold, tmax);
            float psum = 0.f;
#pragma unroll
            for (int c = 0; c < 16; c++) {
                float p = __expf(Ss[row * 64 + cb + c] - mnew);
                Ss[row * 64 + cb + c] = p;
                psum += p;
            }
            psum += __shfl_xor_sync(0xffffffffu, psum, 1);
            psum += __shfl_xor_sync(0xffffffffu, psum, 2);
            float alpha = __expf(mold - mnew);
            if (sub == 0) {
                mrow[row] = mnew;
                lrow[row] = lrow[row] * alpha + psum;
            }
#pragma unroll
            for (int c = 0; c < 16; c++) Os[row * 64 + cb + c] *= alpha;
        }
        __syncthreads();

        // ---- O += P @ V ----
        {
            wmma::fragment<wmma::accumulator, 16, 16, 8, float> oacc[2];
            wmma::load_matrix_sync(oacc[0], &Os[(wr * 16) * 64 + wc * 32], 64,
                                   wmma::mem_row_major);
            wmma::load_matrix_sync(oacc[1], &Os[(wr * 16) * 64 + wc * 32 + 16], 64,
                                   wmma::mem_row_major);
#pragma unroll
            for (int kk = 0; kk < 8; kk++) {
                wmma::fragment<wmma::matrix_a, 16, 16, 8, wmma::precision::tf32,
                               wmma::row_major> af;
                wmma::load_matrix_sync(af, &Ss[(wr * 16) * 64 + kk * 8], 64);
                for (int e = 0; e < af.num_elements; e++)
                    af.x[e] = wmma::__float_to_tf32(af.x[e]);
#pragma unroll
                for (int j = 0; j < 2; j++) {
                    wmma::fragment<wmma::matrix_b, 16, 16, 8, wmma::precision::tf32,
                                   wmma::row_major> bf;
                    wmma::load_matrix_sync(bf, &Vs[(kk * 8) * 64 + wc * 32 + j * 16], 64);
                    for (int e = 0; e < bf.num_elements; e++)
                        bf.x[e] = wmma::__float_to_tf32(bf.x[e]);
                    wmma::mma_sync(oacc[j], af, bf, oacc[j]);
                }
            }
            wmma::store_matrix_sync(&Os[(wr * 16) * 64 + wc * 32], oacc[0], 64,
                                    wmma::mem_row_major);
            wmma::store_matrix_sync(&Os[(wr * 16) * 64 + wc * 32 + 16], oacc[1], 64,
                                    wmma::mem_row_major);
        }
        __syncthreads();
    }

    // finalize: divide by l, write to [s][h*64+d]
    for (int i = tid; i < 1024; i += 256) {
        int r = i >> 4, c = (i & 15) << 2;
        float inv = 1.0f / lrow[r];
        float4 v = *(float4*)&Os[r * 64 + c];
        v.x *= inv; v.y *= inv; v.z *= inv; v.w *= inv;
        *(float4*)&g_O[(q0 + r) * EMB + h * HD + c] = v;
    }
}

// ---------------------------------------------------------------------------

extern "C" void kernel_launch(void* const* d_in, const int* in_sizes, int n_in,
                              void* d_out, int out_size)
{
    const float* x  = (const float*)d_in[0];
    const float* Wq = (const float*)d_in[1];
    const float* bq = (const float*)d_in[2];
    const float* Wk = (const float*)d_in[3];
    const float* bk = (const float*)d_in[4];
    const float* Wv = (const float*)d_in[5];
    const float* bv = (const float*)d_in[6];
    const float* Wo = (const float*)d_in[7];
    const float* bo = (const float*)d_in[8];
    float* out = (float*)d_out;

    float *Qp, *Kp, *Vp, *Op;
    cudaGetSymbolAddress((void**)&Qp, g_Q);
    cudaGetSymbolAddress((void**)&Kp, g_K);
    cudaGetSymbolAddress((void**)&Vp, g_V);
    cudaGetSymbolAddress((void**)&Op, g_O);

    cudaFuncSetAttribute(flash_attn, cudaFuncAttributeMaxDynamicSharedMemorySize,
                         82432);

    dim3 pgrid(EMB / 64, SEQ / 128);
    const float qscale = 0.125f;  // 1/sqrt(64)

    proj_gemm<<<pgrid, 256>>>(x, Wq, bq, Qp, qscale, 1);
    proj_gemm<<<pgrid, 256>>>(x, Wk, bk, Kp, 1.0f, 1);
    proj_gemm<<<pgrid, 256>>>(x, Wv, bv, Vp, 1.0f, 1);

    flash_attn<<<dim3(SEQ / 64, NH), 256, 82432>>>();

    proj_gemm<<<pgrid, 256>>>(Op, Wo, bo, out, 1.0f, 0);
}

// round 2
// speedup vs baseline: 6.6645x; 6.6645x over previous
#include <cuda_runtime.h>
#include <cstdint>

#define SEQ 4096
#define EMB 1024
#define NH  16
#define HD  64
#define KPAD 72   // SMEM row pitch (floats) for K/V/P tiles: 72%32=8 -> conflict-free frag loads

// Scratch: __device__ globals (no runtime allocation).
// g_Q/g_K/g_V hold tf32-rounded bit patterns (stored as float) so flash does no cvt.
__device__ float g_Q[NH * SEQ * HD];   // [h][s][d], pre-scaled by 1/sqrt(64), tf32 bits
__device__ float g_K[NH * SEQ * HD];   // [h][s][d], tf32 bits
__device__ float g_V[NH * SEQ * HD];   // [h][s][d], tf32 bits
__device__ float g_O[SEQ * EMB];       // [s][e] attention output (fp32)

__device__ __forceinline__ uint32_t f2tf(float f) {
    uint32_t u; asm("cvt.rna.tf32.f32 %0, %1;" : "=r"(u) : "f"(f)); return u;
}

// D = A(16x8,row) * B(8x8,col) + D, tf32 in, f32 accum
__device__ __forceinline__ void mma8(float* c, const uint32_t* a, const uint32_t* b) {
    asm volatile(
        "mma.sync.aligned.m16n8k8.row.col.f32.tf32.tf32.f32 "
        "{%0,%1,%2,%3}, {%4,%5,%6,%7}, {%8,%9}, {%0,%1,%2,%3};"
        : "+f"(c[0]), "+f"(c[1]), "+f"(c[2]), "+f"(c[3])
        : "r"(a[0]), "r"(a[1]), "r"(a[2]), "r"(a[3]), "r"(b[0]), "r"(b[1]));
}

__device__ __forceinline__ void cp16(void* dst, const void* src) {
    uint32_t d = (uint32_t)__cvta_generic_to_shared(dst);
    asm volatile("cp.async.cg.shared.global [%0], [%1], 16;" :: "r"(d), "l"(src));
}
__device__ __forceinline__ void cp_commit() { asm volatile("cp.async.commit_group;"); }
__device__ __forceinline__ void cp_wait0()  { asm volatile("cp.async.wait_group 0;" ::: "memory"); }

// ---------------------------------------------------------------------------
// 128x128x32-tile TF32 GEMM body:  C = (A[4096xE] @ W[ExE] + bias) * scale
// 256 threads = 8 warps (4 row-strips of 32 x 2 col-strips of 64).
// A pitch 36, B pitch 136 -> conflict-free fragment loads.
// ---------------------------------------------------------------------------
__device__ __forceinline__ void gemm128(
    const float* __restrict__ A, const float* __restrict__ W,
    const float* __restrict__ bias, float* __restrict__ C,
    float scale, int head_split, int tf32_out,
    uint32_t* As, uint32_t* Bs)
{
    const int tid = threadIdx.x, lane = tid & 31, w = tid >> 5;
    const int g = lane >> 2, tig = lane & 3;
    const int wr = w >> 1, wc = w & 1;
    const int m0 = blockIdx.y * 128, n0 = blockIdx.x * 128;

    float acc[2][8][4];
#pragma unroll
    for (int s = 0; s < 2; s++)
#pragma unroll
        for (int n = 0; n < 8; n++)
#pragma unroll
            for (int i = 0; i < 4; i++) acc[s][n][i] = 0.f;

    float4 ar[4], br[4];
#pragma unroll
    for (int j = 0; j < 4; j++) {
        int idx = tid + j * 256;
        ar[j] = *(const float4*)&A[(m0 + (idx >> 3)) * EMB + ((idx & 7) << 2)];
        br[j] = *(const float4*)&W[(idx >> 5) * EMB + n0 + ((idx & 31) << 2)];
    }

    for (int kt = 0; kt < 32; kt++) {
        __syncthreads();
#pragma unroll
        for (int j = 0; j < 4; j++) {
            int idx = tid + j * 256;
            uint32_t* pa = &As[(idx >> 3) * 36 + ((idx & 7) << 2)];
            pa[0] = f2tf(ar[j].x); pa[1] = f2tf(ar[j].y);
            pa[2] = f2tf(ar[j].z); pa[3] = f2tf(ar[j].w);
            uint32_t* pb = &Bs[(idx >> 5) * 136 + ((idx & 31) << 2)];
            pb[0] = f2tf(br[j].x); pb[1] = f2tf(br[j].y);
            pb[2] = f2tf(br[j].z); pb[3] = f2tf(br[j].w);
        }
        __syncthreads();
        if (kt < 31) {
#pragma unroll
            for (int j = 0; j < 4; j++) {
                int idx = tid + j * 256;
                ar[j] = *(const float4*)&A[(m0 + (idx >> 3)) * EMB + (kt + 1) * 32 + ((idx & 7) << 2)];
                br[j] = *(const float4*)&W[((kt + 1) * 32 + (idx >> 5)) * EMB + n0 + ((idx & 31) << 2)];
            }
        }
#pragma unroll
        for (int kk = 0; kk < 4; kk++) {
            uint32_t af[2][4];
#pragma unroll
            for (int s = 0; s < 2; s++) {
                int rb = wr * 32 + s * 16;
                af[s][0] = As[(rb + g)     * 36 + kk * 8 + tig];
                af[s][1] = As[(rb + g + 8) * 36 + kk * 8 + tig];
                af[s][2] = As[(rb + g)     * 36 + kk * 8 + tig + 4];
                af[s][3] = As[(rb + g + 8) * 36 + kk * 8 + tig + 4];
            }
#pragma unroll
            for (int n = 0; n < 8; n++) {
                uint32_t bb[2];
                bb[0] = Bs[(kk * 8 + tig)     * 136 + wc * 64 + n * 8 + g];
                bb[1] = Bs[(kk * 8 + tig + 4) * 136 + wc * 64 + n * 8 + g];
                mma8(acc[0][n], af[0], bb);
                mma8(acc[1][n], af[1], bb);
            }
        }
    }

    // epilogue: bias + scale (+ optional tf32 rounding) direct from registers
#pragma unroll
    for (int s = 0; s < 2; s++) {
        int r0 = m0 + wr * 32 + s * 16 + g, r1 = r0 + 8;
#pragma unroll
        for (int n = 0; n < 8; n++) {
            int cc = n0 + wc * 64 + n * 8 + 2 * tig;
            float b0 = bias[cc], b1 = bias[cc + 1];
            float v00 = (acc[s][n][0] + b0) * scale, v01 = (acc[s][n][1] + b1) * scale;
            float v10 = (acc[s][n][2] + b0) * scale, v11 = (acc[s][n][3] + b1) * scale;
            if (tf32_out) {
                v00 = __uint_as_float(f2tf(v00)); v01 = __uint_as_float(f2tf(v01));
                v10 = __uint_as_float(f2tf(v10)); v11 = __uint_as_float(f2tf(v11));
            }
            if (head_split) {
                int hh = cc >> 6, d = cc & 63;
                *(float2*)&C[(hh * SEQ + r0) * HD + d] = make_float2(v00, v01);
                *(float2*)&C[(hh * SEQ + r1) * HD + d] = make_float2(v10, v11);
            } else {
                *(float2*)&C[r0 * EMB + cc] = make_float2(v00, v01);
                *(float2*)&C[r1 * EMB + cc] = make_float2(v10, v11);
            }
        }
    }
}

__global__ __launch_bounds__(256) void qkv_gemm(
    const float* __restrict__ x,
    const float* __restrict__ Wq, const float* __restrict__ Wk, const float* __restrict__ Wv,
    const float* __restrict__ bq, const float* __restrict__ bk, const float* __restrict__ bv)
{
    __shared__ uint32_t As[128 * 36];
    __shared__ uint32_t Bs[32 * 136];
    const float* W = Wq; const float* bi = bq; float* C = g_Q; float sc = 0.125f;
    if (blockIdx.z == 1) { W = Wk; bi = bk; C = g_K; sc = 1.0f; }
    if (blockIdx.z == 2) { W = Wv; bi = bv; C = g_V; sc = 1.0f; }
    gemm128(x, W, bi, C, sc, /*head_split=*/1, /*tf32_out=*/1, As, Bs);
}

__global__ __launch_bounds__(256) void out_gemm(
    const float* __restrict__ Wo, const float* __restrict__ bo, float* __restrict__ out)
{
    __shared__ uint32_t As[128 * 36];
    __shared__ uint32_t Bs[32 * 136];
    gemm128(g_O, Wo, bo, out, 1.0f, /*head_split=*/0, /*tf32_out=*/0, As, Bs);
}

// ---------------------------------------------------------------------------
// Flash attention: 1 CTA per (128 q-rows, head). 8 warps x 16 q-rows each.
// S and O live in registers; softmax via quad shuffles; P round-trips through
// a per-warp SMEM strip; K/V tiles cp.async double-buffered (tf32 pre-converted).
// Dynamic SMEM: Ks[2]+Vs[2] (4*64*72 u32) + Ps (8*16*72 u32) = 110592 B.
// ---------------------------------------------------------------------------
__global__ __launch_bounds__(256) void flash_attn()
{
    extern __shared__ uint32_t shm[];
    uint32_t* KsB = shm;                    // 2 * 64*72
    uint32_t* VsB = shm + 2 * 64 * KPAD;    // 2 * 64*72
    uint32_t* Ps  = shm + 4 * 64 * KPAD;    // 8 * 16*72

    const int h = blockIdx.y;
    const int q0 = blockIdx.x * 128;
    const int tid = threadIdx.x, lane = tid & 31, w = tid >> 5;
    const int g = lane >> 2, tig = lane & 3;
    uint32_t* myP = Ps + w * 16 * KPAD;

    // ---- stage this warp's 16x64 Q strip (tf32 bits) -> fragments in regs ----
    const float* Qg = g_Q + (size_t)(h * SEQ + q0 + w * 16) * HD;
#pragma unroll
    for (int j = 0; j < 8; j++) {
        int idx = lane + j * 32;                 // 256 float4 chunks
        int r = idx >> 4, c4 = (idx & 15) << 2;
        *(uint4*)&myP[r * KPAD + c4] = *(const uint4*)&Qg[r * HD + c4];
    }
    __syncwarp();
    uint32_t qf[8][4];
#pragma unroll
    for (int kk = 0; kk < 8; kk++) {
        qf[kk][0] = myP[g       * KPAD + kk * 8 + tig];
        qf[kk][1] = myP[(g + 8) * KPAD + kk * 8 + tig];
        qf[kk][2] = myP[g       * KPAD + kk * 8 + tig + 4];
        qf[kk][3] = myP[(g + 8) * KPAD + kk * 8 + tig + 4];
    }

    float oacc[8][4];
#pragma unroll
    for (int n = 0; n < 8; n++)
#pragma unroll
        for (int i = 0; i < 4; i++) oacc[n][i] = 0.f;
    float m0 = -1e30f, m1 = -1e30f, l0 = 0.f, l1 = 0.f;

    const float* Kh = g_K + (size_t)h * SEQ * HD;
    const float* Vh = g_V + (size_t)h * SEQ * HD;

    // issue tile 0
    {
#pragma unroll
        for (int j = 0; j < 4; j++) {
            int idx = tid + j * 256;               // 1024 chunks over 64x64
            int r = idx >> 4, c4 = (idx & 15) << 2;
            cp16(&KsB[r * KPAD + c4], &Kh[r * HD + c4]);
            cp16(&VsB[r * KPAD + c4], &Vh[r * HD + c4]);
        }
        cp_commit();
    }

    const int NT = SEQ / 64;
    for (int t = 0; t < NT; t++) {
        cp_wait0();
        __syncthreads();           // tile t visible; prior compute done -> safe to refill other buf
        if (t + 1 < NT) {
            int buf = (t + 1) & 1;
            const float* Kt = Kh + (size_t)(t + 1) * 64 * HD;
            const float* Vt = Vh + (size_t)(t + 1) * 64 * HD;
#pragma unroll
            for (int j = 0; j < 4; j++) {
                int idx = tid + j * 256;
                int r = idx >> 4, c4 = (idx & 15) << 2;
                cp16(&KsB[buf * 64 * KPAD + r * KPAD + c4], &Kt[r * HD + c4]);
                cp16(&VsB[buf * 64 * KPAD + r * KPAD + c4], &Vt[r * HD + c4]);
            }
            cp_commit();
        }
        const uint32_t* Ks = KsB + (t & 1) * 64 * KPAD;
        const uint32_t* Vs = VsB + (t & 1) * 64 * KPAD;

        // ---- S = Q @ K^T : 8 n-tiles of m16n8, accumulate over 8 k-tiles ----
        float sacc[8][4];
#pragma unroll
        for (int n = 0; n < 8; n++)
#pragma unroll
            for (int i = 0; i < 4; i++) sacc[n][i] = 0.f;
#pragma unroll
        for (int kk = 0; kk < 8; kk++) {
#pragma unroll
            for (int n = 0; n < 8; n++) {
                uint32_t bb[2];
                bb[0] = Ks[(n * 8 + g) * KPAD + kk * 8 + tig];
                bb[1] = Ks[(n * 8 + g) * KPAD + kk * 8 + tig + 4];
                mma8(sacc[n], qf[kk], bb);
            }
        }

        // ---- online softmax in registers (rows g and g+8 of this warp strip) ----
        float mx0 = -1e30f, mx1 = -1e30f;
#pragma unroll
        for (int n = 0; n < 8; n++) {
            mx0 = fmaxf(mx0, fmaxf(sacc[n][0], sacc[n][1]));
            mx1 = fmaxf(mx1, fmaxf(sacc[n][2], sacc[n][3]));
        }
        mx0 = fmaxf(mx0, __shfl_xor_sync(0xffffffffu, mx0, 1));
        mx0 = fmaxf(mx0, __shfl_xor_sync(0xffffffffu, mx0, 2));
        mx1 = fmaxf(mx1, __shfl_xor_sync(0xffffffffu, mx1, 1));
        mx1 = fmaxf(mx1, __shfl_xor_sync(0xffffffffu, mx1, 2));
        float nm0 = fmaxf(m0, mx0), nm1 = fmaxf(m1, mx1);
        float a0 = __expf(m0 - nm0), a1 = __expf(m1 - nm1);
        float s0 = 0.f, s1 = 0.f;
#pragma unroll
        for (int n = 0; n < 8; n++) {
            float p00 = __expf(sacc[n][0] - nm0);
            float p01 = __expf(sacc[n][1] - nm0);
            float p10 = __expf(sacc[n][2] - nm1);
            float p11 = __expf(sacc[n][3] - nm1);
            s0 += p00 + p01; s1 += p10 + p11;
            uint2 lo = make_uint2(f2tf(p00), f2tf(p01));
            uint2 hi = make_uint2(f2tf(p10), f2tf(p11));
            *(uint2*)&myP[g       * KPAD + n * 8 + 2 * tig] = lo;
            *(uint2*)&myP[(g + 8) * KPAD + n * 8 + 2 * tig] = hi;
        }
        s0 += __shfl_xor_sync(0xffffffffu, s0, 1);
        s0 += __shfl_xor_sync(0xffffffffu, s0, 2);
        s1 += __shfl_xor_sync(0xffffffffu, s1, 1);
        s1 += __shfl_xor_sync(0xffffffffu, s1, 2);
        m0 = nm0; m1 = nm1;
        l0 = l0 * a0 + s0; l1 = l1 * a1 + s1;
#pragma unroll
        for (int n = 0; n < 8; n++) {
            oacc[n][0] *= a0; oacc[n][1] *= a0;
            oacc[n][2] *= a1; oacc[n][3] *= a1;
        }
        __syncwarp();

        // ---- O += P @ V ----
#pragma unroll
        for (int kk = 0; kk < 8; kk++) {
            uint32_t pa[4];
            pa[0] = myP[g       * KPAD + kk * 8 + tig];
            pa[1] = myP[(g + 8) * KPAD + kk * 8 + tig];
            pa[2] = myP[g       * KPAD + kk * 8 + tig + 4];
            pa[3] = myP[(g + 8) * KPAD + kk * 8 + tig + 4];
#pragma unroll
            for (int n = 0; n < 8; n++) {
                uint32_t vb[2];
                vb[0] = Vs[(kk * 8 + tig)     * KPAD + n * 8 + g];
                vb[1] = Vs[(kk * 8 + tig + 4) * KPAD + n * 8 + g];
                mma8(oacc[n], pa, vb);
            }
        }
    }

    // ---- finalize: O/l -> g_O[s][h*64+d] ----
    float inv0 = 1.0f / l0, inv1 = 1.0f / l1;
    int r0 = q0 + w * 16 + g, r1 = r0 + 8;
#pragma unroll
    for (int n = 0; n < 8; n++) {
        int col = h * HD + n * 8 + 2 * tig;
        *(float2*)&g_O[r0 * EMB + col] = make_float2(oacc[n][0] * inv0, oacc[n][1] * inv0);
        *(float2*)&g_O[r1 * EMB + col] = make_float2(oacc[n][2] * inv1, oacc[n][3] * inv1);
    }
}

// ---------------------------------------------------------------------------

extern "C" void kernel_launch(void* const* d_in, const int* in_sizes, int n_in,
                              void* d_out, int out_size)
{
    const float* x  = (const float*)d_in[0];
    const float* Wq = (const float*)d_in[1];
    const float* bq = (const float*)d_in[2];
    const float* Wk = (const float*)d_in[3];
    const float* bk = (const float*)d_in[4];
    const float* Wv = (const float*)d_in[5];
    const float* bv = (const float*)d_in[6];
    const float* Wo = (const float*)d_in[7];
    const float* bo = (const float*)d_in[8];
    float* out = (float*)d_out;

    cudaFuncSetAttribute(flash_attn, cudaFuncAttributeMaxDynamicSharedMemorySize, 110592);

    qkv_gemm<<<dim3(EMB / 128, SEQ / 128, 3), 256>>>(x, Wq, Wk, Wv, bq, bk, bv);
    flash_attn<<<dim3(SEQ / 128, NH), 256, 110592>>>();
    out_gemm<<<dim3(EMB / 128, SEQ / 128), 256>>>(Wo, bo, out);
}